// round 9
// baseline (speedup 1.0000x reference)
#include <cuda_runtime.h>
#include <cuda_bf16.h>

// PitchLoss: reference's (N,B,L) broadcast collapses analytically because
// mask[n,b,l] = c[b,n] is constant over l:
//   diff[b,n] = | c[b,n] * (mean_g[b] - mean_t[b]) / (c[b,n] + 1e-6) |
//   loss      = mean_{b,n} relu(diff - 0.5)
// with c[b,n] = -(# onsets at idx>=1 in segment n) - (n==0 ? offsets[b,0] : 0),
// zeroed for n >= n_notes[b]; segment index = inclusive cumsum of offsets.
//
// R9: evidence so far: body structure moves kernel time <=1us around 7.5us
// (occ 13->46%, issue 8->25%, cp.async, batching: all ~neutral); ~4.4us is
// launch/ramp floor. The one remaining lever is the post-histogram critical
// path: collapse the whole epilogue into warp 0 (4 notes/lane straight from
// s_counts, one warp reduce, lane0 fires the packed count+value atomic).
// Deletes the 3rd __syncthreads, the s_red smem round-trip and one reduce
// stage; warps 1-7 retire early. Packed 64-bit atomic (count in bits[57:64),
// fixed-point sum below) makes the last arrival's return value the complete
// sum: no threadfence, no partial array, no readback; integer adds ->
// bit-deterministic across graph replays.

#define BATCH 64
#define LEN   4096
#define NMAX  128
#define T1    256
#define CHUNK (LEN / T1)   // 16 elements / thread
#define NV    (CHUNK / 4)
#define FULLM 0xffffffffu
#define CNT_SHIFT 57
#define VAL_MASK  ((1ULL << CNT_SHIFT) - 1ULL)
#define FP_SCALE  68719476736.0f   // 2^36

__device__ unsigned long long g_pack = 0ULL;

__global__ __launch_bounds__(T1)
void pitch_fused_kernel(const float* __restrict__ gen_f0,
                        const float* __restrict__ contours,
                        const int*   __restrict__ onsets,
                        const int*   __restrict__ offsets,
                        float*       __restrict__ out)
{
    const int b    = blockIdx.x;
    const int tid  = threadIdx.x;
    const int lane = tid & 31;
    const int wid  = tid >> 5;           // 8 warps

    const float4* __restrict__ gr  = (const float4*)(gen_f0   + (size_t)b * LEN)     + tid * NV;
    const float4* __restrict__ tr  = (const float4*)(contours + (size_t)b * 2 * LEN) + tid * NV;
    const int4*   __restrict__ on  = (const int4*)(onsets  + (size_t)b * LEN) + tid * NV;
    const int4*   __restrict__ off = (const int4*)(offsets + (size_t)b * LEN) + tid * NV;

    __shared__ int   s_counts[NMAX];
    __shared__ int   s_wosum[8];
    __shared__ float s_wg[8], s_wt[8];

    if (tid < NMAX) s_counts[tid] = 0;

    // ---- loads: sums + 16-bit on/off masks ----
    float sg = 0.f, st = 0.f;
    unsigned offm = 0, onm = 0;
#pragma unroll
    for (int j = 0; j < NV; j++) {
        const float4 g4 = gr[j];
        const float4 t4 = tr[j];
        const int4   o4 = off[j];
        const int4   n4 = on[j];
        sg += (g4.x + g4.y) + (g4.z + g4.w);
        st += (t4.x + t4.y) + (t4.z + t4.w);
        const int s = 4 * j;
        offm |= ((unsigned)o4.x << s) | ((unsigned)o4.y << (s + 1))
              | ((unsigned)o4.z << (s + 2)) | ((unsigned)o4.w << (s + 3));
        onm  |= ((unsigned)n4.x << s) | ((unsigned)n4.y << (s + 1))
              | ((unsigned)n4.z << (s + 2)) | ((unsigned)n4.w << (s + 3));
    }
    const int osum = __popc(offm);

    // ---- warp-level: inclusive scan of osum, reduce sg/st ----
    int incl = osum;
#pragma unroll
    for (int d = 1; d < 32; d <<= 1) {
        int v = __shfl_up_sync(FULLM, incl, d);
        if (lane >= d) incl += v;
    }
    float rg = sg, rt = st;
#pragma unroll
    for (int d = 16; d > 0; d >>= 1) {
        rg += __shfl_down_sync(FULLM, rg, d);
        rt += __shfl_down_sync(FULLM, rt, d);
    }
    if (lane == 31) s_wosum[wid] = incl;
    if (lane == 0) { s_wg[wid] = rg; s_wt[wid] = rt; }
    __syncthreads();                      // barrier 1

    // ---- cross-warp prefix + scatter onset counts ----
    int wpre = 0;
#pragma unroll
    for (int w = 0; w < 8; w++) wpre += (w < wid) ? s_wosum[w] : 0;
    const int excl = wpre + incl - osum;   // exclusive offset-prefix of this thread

    unsigned m = onm;
    if (tid == 0) m &= ~1u;                // reference masks onsets at idx==0
    while (m) {
        const int j = __ffs(m) - 1;
        m &= m - 1;
        const int seg = excl + __popc(offm & ((2u << j) - 1u));  // inclusive cumsum at l
        if (seg < NMAX) atomicAdd(&s_counts[seg], 1);
    }
    __syncthreads();                      // barrier 2 (histogram complete)

    // ---- epilogue: warp 0 only; warps 1-7 retire ----
    if (wid == 0) {
        int   n_notes = 0;
        float tg = 0.f, tt = 0.f;
#pragma unroll
        for (int w = 0; w < 8; w++) { n_notes += s_wosum[w]; tg += s_wg[w]; tt += s_wt[w]; }
        const float dd = (tg - tt) * (1.0f / LEN);

        float val = 0.f;
#pragma unroll
        for (int k = 0; k < 4; k++) {
            const int n = lane + 32 * k;
            float c = -(float)s_counts[n];
            if (n == 0) c -= (float)(offm & 1u);  // lane0 == tid0 holds offsets[b,0]
            if (n >= n_notes) c = 0.f;
            const float diff = fabsf(c * dd / (c + 1e-6f));
            val += fmaxf(diff - 0.5f, 0.f);
        }
#pragma unroll
        for (int d = 16; d > 0; d >>= 1) val += __shfl_down_sync(FULLM, val, d);

        // ---- single packed atomic: count in high bits, fixed-point sum low ----
        if (lane == 0) {
            const unsigned long long q =
                (unsigned long long)__float2ll_rn(val * FP_SCALE);
            const unsigned long long add = (1ULL << CNT_SHIFT) + q;
            const unsigned long long old = atomicAdd(&g_pack, add);
            if ((old >> CNT_SHIFT) == (unsigned long long)(BATCH - 1)) {
                const unsigned long long tot = (old + add) & VAL_MASK;
                out[0] = (float)((double)tot * (1.0 / (double)FP_SCALE)
                                  * (1.0 / (NMAX * BATCH)));
                g_pack = 0ULL;   // all 64 adds landed: safe to rearm for replay
            }
        }
    }
}

extern "C" void kernel_launch(void* const* d_in, const int* in_sizes, int n_in,
                              void* d_out, int out_size)
{
    const float* gen_f0   = (const float*)d_in[0];
    const float* contours = (const float*)d_in[1];
    const int*   onsets   = (const int*)d_in[2];
    const int*   offsets  = (const int*)d_in[3];
    // d_in[4] = n_notes_max (compile-time NMAX=128 for this shape)

    pitch_fused_kernel<<<BATCH, T1>>>(gen_f0, contours, onsets, offsets, (float*)d_out);
}

// round 10
// speedup vs baseline: 1.0895x; 1.0895x over previous
#include <cuda_runtime.h>
#include <cuda_bf16.h>

// PitchLoss: reference's (N,B,L) broadcast collapses analytically because
// mask[n,b,l] = c[b,n] is constant over l:
//   diff[b,n] = | c[b,n] * (mean_g[b] - mean_t[b]) / (c[b,n] + 1e-6) |
//   loss      = mean_{b,n} relu(diff - 0.5)
// with c[b,n] = -(# onsets at idx>=1 in segment n) - (n==0 ? offsets[b,0] : 0),
// zeroed for n >= n_notes[b]; segment index = inclusive cumsum of offsets.
//
// R10 = revert to R8 (best measured: kernel 7.42us / wall 8.22us) after the
// R9 warp-0 epilogue serialization regressed (+0.4us). One free overlap
// added: the n_notes/tg/tt combine depends only on barrier-1 data, so it is
// hoisted above barrier 2 to hide under the histogram scatter. Tail stays
// the single packed 64-bit atomic (count in bits[57:64), fixed-point sum
// below): last arrival's return value IS the complete sum -> no threadfence,
// no partial array, no readback; integer adds are commutative ->
// bit-deterministic across graph replays.

#define BATCH 64
#define LEN   4096
#define NMAX  128
#define T1    256
#define CHUNK (LEN / T1)   // 16 elements / thread
#define NV    (CHUNK / 4)
#define FULLM 0xffffffffu
#define CNT_SHIFT 57
#define VAL_MASK  ((1ULL << CNT_SHIFT) - 1ULL)
#define FP_SCALE  68719476736.0f   // 2^36

__device__ unsigned long long g_pack = 0ULL;

__global__ __launch_bounds__(T1)
void pitch_fused_kernel(const float* __restrict__ gen_f0,
                        const float* __restrict__ contours,
                        const int*   __restrict__ onsets,
                        const int*   __restrict__ offsets,
                        float*       __restrict__ out)
{
    const int b    = blockIdx.x;
    const int tid  = threadIdx.x;
    const int lane = tid & 31;
    const int wid  = tid >> 5;           // 8 warps

    const float4* __restrict__ gr  = (const float4*)(gen_f0   + (size_t)b * LEN)     + tid * NV;
    const float4* __restrict__ tr  = (const float4*)(contours + (size_t)b * 2 * LEN) + tid * NV;
    const int4*   __restrict__ on  = (const int4*)(onsets  + (size_t)b * LEN) + tid * NV;
    const int4*   __restrict__ off = (const int4*)(offsets + (size_t)b * LEN) + tid * NV;

    __shared__ int   s_counts[NMAX];
    __shared__ int   s_wosum[8];
    __shared__ float s_wg[8], s_wt[8];
    __shared__ float s_red[4];

    if (tid < NMAX) s_counts[tid] = 0;

    // ---- loads: sums + 16-bit on/off masks ----
    float sg = 0.f, st = 0.f;
    unsigned offm = 0, onm = 0;
#pragma unroll
    for (int j = 0; j < NV; j++) {
        const float4 g4 = gr[j];
        const float4 t4 = tr[j];
        const int4   o4 = off[j];
        const int4   n4 = on[j];
        sg += (g4.x + g4.y) + (g4.z + g4.w);
        st += (t4.x + t4.y) + (t4.z + t4.w);
        const int s = 4 * j;
        offm |= ((unsigned)o4.x << s) | ((unsigned)o4.y << (s + 1))
              | ((unsigned)o4.z << (s + 2)) | ((unsigned)o4.w << (s + 3));
        onm  |= ((unsigned)n4.x << s) | ((unsigned)n4.y << (s + 1))
              | ((unsigned)n4.z << (s + 2)) | ((unsigned)n4.w << (s + 3));
    }
    const int osum = __popc(offm);

    // ---- warp-level: inclusive scan of osum, reduce sg/st ----
    int incl = osum;
#pragma unroll
    for (int d = 1; d < 32; d <<= 1) {
        int v = __shfl_up_sync(FULLM, incl, d);
        if (lane >= d) incl += v;
    }
#pragma unroll
    for (int d = 16; d > 0; d >>= 1) {
        sg += __shfl_down_sync(FULLM, sg, d);
        st += __shfl_down_sync(FULLM, st, d);
    }
    if (lane == 31) s_wosum[wid] = incl;
    if (lane == 0) { s_wg[wid] = sg; s_wt[wid] = st; }
    __syncthreads();                      // barrier 1

    // ---- cross-warp prefix + scatter onset counts ----
    int wpre = 0;
#pragma unroll
    for (int w = 0; w < 8; w++) wpre += (w < wid) ? s_wosum[w] : 0;
    const int excl = wpre + incl - osum;   // exclusive offset-prefix of this thread

    unsigned m = onm;
    if (tid == 0) m &= ~1u;                // reference masks onsets at idx==0
    while (m) {
        const int j = __ffs(m) - 1;
        m &= m - 1;
        const int seg = excl + __popc(offm & ((2u << j) - 1u));  // inclusive cumsum at l
        if (seg < NMAX) atomicAdd(&s_counts[seg], 1);
    }

    // ---- combine (barrier-1 data only): hidden under the scatter above ----
    int   n_notes = 0;
    float tg = 0.f, tt = 0.f;
#pragma unroll
    for (int w = 0; w < 8; w++) { n_notes += s_wosum[w]; tg += s_wg[w]; tt += s_wt[w]; }
    const float dd = (tg - tt) * (1.0f / LEN);

    __syncthreads();                      // barrier 2 (histogram complete)

    // ---- per-note loss, block reduce (threads 0-127 = one note each) ----
    float val = 0.f;
    if (tid < NMAX) {
        float c = -(float)s_counts[tid];
        if (tid == 0) c -= (float)(offm & 1u);   // tid0's chunk holds offsets[b,0]
        if (tid >= n_notes) c = 0.f;
        const float diff = fabsf(c * dd / (c + 1e-6f));
        val = fmaxf(diff - 0.5f, 0.f);
    }
#pragma unroll
    for (int d = 16; d > 0; d >>= 1) val += __shfl_down_sync(FULLM, val, d);
    if (lane == 0 && wid < 4) s_red[wid] = val;   // warps 0-3 hold tid<128
    __syncthreads();                      // barrier 3

    // ---- single packed atomic: count in high bits, fixed-point sum low ----
    if (tid == 0) {
        const float bs = (s_red[0] + s_red[1]) + (s_red[2] + s_red[3]);
        const unsigned long long q =
            (unsigned long long)__float2ll_rn(bs * FP_SCALE);
        const unsigned long long add = (1ULL << CNT_SHIFT) + q;
        const unsigned long long old = atomicAdd(&g_pack, add);
        if ((old >> CNT_SHIFT) == (unsigned long long)(BATCH - 1)) {
            const unsigned long long tot = (old + add) & VAL_MASK;
            out[0] = (float)((double)tot * (1.0 / (double)FP_SCALE)
                              * (1.0 / (NMAX * BATCH)));
            g_pack = 0ULL;   // all 64 adds landed (count==64): safe to rearm
        }
    }
}

extern "C" void kernel_launch(void* const* d_in, const int* in_sizes, int n_in,
                              void* d_out, int out_size)
{
    const float* gen_f0   = (const float*)d_in[0];
    const float* contours = (const float*)d_in[1];
    const int*   onsets   = (const int*)d_in[2];
    const int*   offsets  = (const int*)d_in[3];
    // d_in[4] = n_notes_max (compile-time NMAX=128 for this shape)

    pitch_fused_kernel<<<BATCH, T1>>>(gen_f0, contours, onsets, offsets, (float*)d_out);
}